// round 10
// baseline (speedup 1.0000x reference)
#include <cuda_runtime.h>
#include <cuda_bf16.h>
#include <cstdint>

// Wilson Dslash, 32^4 lattice, half-spinor formulation.
// l1tex-wavefront-bound regime --> move psi line loads and output stores onto
// the TMA/bulk-copy engine (cp.async.bulk), which bypasses l1tex entirely.
// Each psi t-line is a contiguous 1536B chunk: per-warp bulk copy into a
// per-warp smem strip, completion via a per-warp mbarrier whose latency hides
// under the U staging LDGs. U (36B-strided rows, not bulk-copyable) stays on
// the proven scalar coalesced LDG/STS path with conflict-free stride-9 readback.
// Output: scale -> conflict-free STS -> bulk store smem->global.
// t-hops reuse the warp's own line staged once. No block barriers.

#define LAT 32
#define VOL (LAT * LAT * LAT * LAT)
#define NT 256
#define NWARP (NT / 32)

__device__ __forceinline__ uint32_t smem_u32(const void* p) {
    uint32_t a;
    asm("{ .reg .u64 t; cvta.to.shared.u64 t, %1; cvt.u32.u64 %0, t; }"
        : "=r"(a) : "l"(p));
    return a;
}

__global__ __launch_bounds__(NT, 2)
void dslash_kernel(const float* __restrict__ psi_re, const float* __restrict__ psi_im,
                   const float* __restrict__ U_re,   const float* __restrict__ U_im,
                   float* __restrict__ out)
{
    __shared__ float4 sPr4[NWARP][96];   // one t-line of psi re (32 sites x 3 float4)
    __shared__ float4 sPi4[NWARP][96];
    __shared__ float  sUr[NWARP][288];   // one t-line of U (32 sites x 9)
    __shared__ float  sUi[NWARP][288];
    __shared__ __align__(8) unsigned long long mbar[NWARP];

    const int tid    = threadIdx.x;
    const int lane   = tid & 31;
    const int w      = tid >> 5;
    const int base_w = blockIdx.x * NT + w * 32;   // 32-aligned t-line base
    const int site   = base_w + lane;

    const uint32_t mb  = smem_u32(&mbar[w]);
    const uint32_t dPr = smem_u32(&sPr4[w][0]);
    const uint32_t dPi = smem_u32(&sPi4[w][0]);

    if (lane == 0)
        asm volatile("mbarrier.init.shared.b64 [%0], 1;" :: "r"(mb) : "memory");
    __syncwarp();

    int ph = 0;   // mbarrier phase parity

    float accr[12], acci[12];
#pragma unroll
    for (int k = 0; k < 12; k++) { accr[k] = 0.f; acci[k] = 0.f; }

#pragma unroll
    for (int mu = 0; mu < 4; mu++) {
        const int shift = (mu == 0) ? 15 : (mu == 1) ? 10 : (mu == 2) ? 5 : 0;
        const int sm = 1 << shift;
        const int cmw = (base_w >> shift) & 31;            // warp-uniform coord
        const int fdelta = (cmw == 31) ? -31 * sm : sm;    // +mu line offset
        const int bdelta = (cmw == 0)  ?  31 * sm : -sm;   // -mu line offset

#pragma unroll 1
        for (int hop = 0; hop < 2; hop++) {   // 0 = fwd (P-, U), 1 = bwd (P+, U^dag)
            const float s = hop ? 1.f : -1.f;
            const bool do_tma = (mu < 3) || (hop == 0);    // mu==3 line staged once

            // ---- issue psi line bulk-copy (bypasses l1tex) ----
            if (do_tma && lane == 0) {
                const int pline = (mu < 3) ? (base_w + (hop ? bdelta : fdelta))
                                           : base_w;
                // order prior generic reads of sPr4/sPi4 before async overwrite
                asm volatile("fence.proxy.async.shared::cta;" ::: "memory");
                asm volatile("mbarrier.arrive.expect_tx.shared.b64 _, [%0], %1;"
                             :: "r"(mb), "r"(3072) : "memory");
                const float* srcr = psi_re + (size_t)pline * 12;
                const float* srci = psi_im + (size_t)pline * 12;
                asm volatile(
                    "cp.async.bulk.shared::cluster.global.mbarrier::complete_tx::bytes "
                    "[%0], [%1], %2, [%3];"
                    :: "r"(dPr), "l"(srcr), "r"(1536), "r"(mb) : "memory");
                asm volatile(
                    "cp.async.bulk.shared::cluster.global.mbarrier::complete_tx::bytes "
                    "[%0], [%1], %2, [%3];"
                    :: "r"(dPi), "l"(srci), "r"(1536), "r"(mb) : "memory");
            }

            // ---- stage U t-line (coalesced scalar; TMA latency hides here) ----
            const bool load_u = (mu < 3) || (hop == 0);
            if (load_u) {
                const int ubase = (mu < 3 && hop) ? (base_w + bdelta) : base_w;
#pragma unroll
                for (int it = 0; it < 9; it++) {
                    const int idx = it * 32 + lane;
                    const int l = idx / 9;
                    const int k = idx - l * 9;
                    const size_t g = ((size_t)(ubase + l) * 4 + mu) * 9 + k;
                    sUr[w][idx] = U_re[g];
                    sUi[w][idx] = U_im[g];
                }
            }
            __syncwarp();   // U visible warp-wide

            // ---- wait for psi bulk-copy completion ----
            if (do_tma) {
                uint32_t done;
                do {
                    asm volatile(
                        "{ .reg .pred p; "
                        "mbarrier.try_wait.parity.shared::cta.b64 p, [%1], %2; "
                        "selp.b32 %0, 1, 0, p; }"
                        : "=r"(done) : "r"(mb), "r"(ph) : "memory");
                } while (!done);
                ph ^= 1;
            }

            // ---- read neighbor spinor from smem (conflict-free LDS.128) ----
            const int psl = (mu == 3) ? ((lane + (hop ? 31 : 1)) & 31) : lane;
            float pr[12], pi[12];
#pragma unroll
            for (int r = 0; r < 3; r++) {
                float4 a = sPr4[w][psl * 3 + r];
                pr[4*r+0] = a.x; pr[4*r+1] = a.y; pr[4*r+2] = a.z; pr[4*r+3] = a.w;
                float4 b = sPi4[w][psl * 3 + r];
                pi[4*r+0] = b.x; pi[4*r+1] = b.y; pi[4*r+2] = b.z; pi[4*r+3] = b.w;
            }

            // ---- project to half-spinor (mu static, s runtime) ----
            float hr0[3], hi0[3], hr1[3], hi1[3];
#pragma unroll
            for (int c = 0; c < 3; c++) {
                if (mu == 0) {          // h0 = p0 + s*i*p3 ; h1 = p1 + s*i*p2
                    hr0[c] = pr[c]   - s * pi[9+c];  hi0[c] = pi[c]   + s * pr[9+c];
                    hr1[c] = pr[3+c] - s * pi[6+c];  hi1[c] = pi[3+c] + s * pr[6+c];
                } else if (mu == 1) {   // h0 = p0 - s*p3 ; h1 = p1 + s*p2
                    hr0[c] = pr[c]   - s * pr[9+c];  hi0[c] = pi[c]   - s * pi[9+c];
                    hr1[c] = pr[3+c] + s * pr[6+c];  hi1[c] = pi[3+c] + s * pi[6+c];
                } else if (mu == 2) {   // h0 = p0 + s*i*p2 ; h1 = p1 - s*i*p3
                    hr0[c] = pr[c]   - s * pi[6+c];  hi0[c] = pi[c]   + s * pr[6+c];
                    hr1[c] = pr[3+c] + s * pi[9+c];  hi1[c] = pi[3+c] - s * pr[9+c];
                } else {                // h0 = p0 + s*p2 ; h1 = p1 + s*p3
                    hr0[c] = pr[c]   + s * pr[6+c];  hi0[c] = pi[c]   + s * pi[6+c];
                    hr1[c] = pr[3+c] + s * pr[9+c];  hi1[c] = pi[3+c] + s * pi[9+c];
                }
            }

            // ---- U read + color matvec: static per-hop branch ----
            const int usl = (mu == 3 && hop) ? ((lane + 31) & 31) : lane;
            const float* br = &sUr[w][usl * 9];
            const float* bi = &sUi[w][usl * 9];

            float xr0[3], xi0[3], xr1[3], xi1[3];
            if (hop == 0) {
#pragma unroll
                for (int i = 0; i < 3; i++) {
                    float r0 = 0.f, m0 = 0.f, r1 = 0.f, m1 = 0.f;
#pragma unroll
                    for (int j = 0; j < 3; j++) {
                        const float a = br[3*i+j], b = bi[3*i+j];
                        r0 += a * hr0[j] - b * hi0[j];
                        m0 += a * hi0[j] + b * hr0[j];
                        r1 += a * hr1[j] - b * hi1[j];
                        m1 += a * hi1[j] + b * hr1[j];
                    }
                    xr0[i] = r0; xi0[i] = m0; xr1[i] = r1; xi1[i] = m1;
                }
            } else {
#pragma unroll
                for (int i = 0; i < 3; i++) {
                    float r0 = 0.f, m0 = 0.f, r1 = 0.f, m1 = 0.f;
#pragma unroll
                    for (int j = 0; j < 3; j++) {
                        const float a = br[3*j+i], b = bi[3*j+i];   // U^dag
                        r0 += a * hr0[j] + b * hi0[j];
                        m0 += a * hi0[j] - b * hr0[j];
                        r1 += a * hr1[j] + b * hi1[j];
                        m1 += a * hi1[j] - b * hr1[j];
                    }
                    xr0[i] = r0; xi0[i] = m0; xr1[i] = r1; xi1[i] = m1;
                }
            }

            // ---- accumulate with spin reconstruction ----
#pragma unroll
            for (int i = 0; i < 3; i++) {
                accr[i]   += xr0[i];  acci[i]   += xi0[i];
                accr[3+i] += xr1[i];  acci[3+i] += xi1[i];
                if (mu == 0) {          // acc2 += -s*i*x1 ; acc3 += -s*i*x0
                    accr[6+i] += s * xi1[i];  acci[6+i] -= s * xr1[i];
                    accr[9+i] += s * xi0[i];  acci[9+i] -= s * xr0[i];
                } else if (mu == 1) {   // acc2 += s*x1 ; acc3 += -s*x0
                    accr[6+i] += s * xr1[i];  acci[6+i] += s * xi1[i];
                    accr[9+i] -= s * xr0[i];  acci[9+i] -= s * xi0[i];
                } else if (mu == 2) {   // acc2 += -s*i*x0 ; acc3 += s*i*x1
                    accr[6+i] += s * xi0[i];  acci[6+i] -= s * xr0[i];
                    accr[9+i] -= s * xi1[i];  acci[9+i] += s * xr1[i];
                } else {                // acc2 += s*x0 ; acc3 += s*x1
                    accr[6+i] += s * xr0[i];  acci[6+i] += s * xi0[i];
                    accr[9+i] += s * xr1[i];  acci[9+i] += s * xi1[i];
                }
            }
            __syncwarp();   // buffers reused next stage
        }
    }

    // ---- scale by -0.5, transpose through smem, bulk-store coalesced ----
#pragma unroll
    for (int r = 0; r < 3; r++) {
        float4 a, b;
        a.x = -0.5f * accr[4*r+0]; a.y = -0.5f * accr[4*r+1];
        a.z = -0.5f * accr[4*r+2]; a.w = -0.5f * accr[4*r+3];
        b.x = -0.5f * acci[4*r+0]; b.y = -0.5f * acci[4*r+1];
        b.z = -0.5f * acci[4*r+2]; b.w = -0.5f * acci[4*r+3];
        sPr4[w][lane * 3 + r] = a;     // stride-3 float4: conflict-free
        sPi4[w][lane * 3 + r] = b;
    }
    __syncwarp();
    if (lane == 0) {
        asm volatile("fence.proxy.async.shared::cta;" ::: "memory");
        float* gr = out + (size_t)base_w * 12;
        float* gi = out + (size_t)(VOL + base_w) * 12;
        asm volatile("cp.async.bulk.global.shared::cta.bulk_group [%0], [%1], %2;"
                     :: "l"(gr), "r"(dPr), "r"(1536) : "memory");
        asm volatile("cp.async.bulk.global.shared::cta.bulk_group [%0], [%1], %2;"
                     :: "l"(gi), "r"(dPi), "r"(1536) : "memory");
        asm volatile("cp.async.bulk.commit_group;" ::: "memory");
        asm volatile("cp.async.bulk.wait_group 0;" ::: "memory");
    }
}

extern "C" void kernel_launch(void* const* d_in, const int* in_sizes, int n_in,
                              void* d_out, int out_size) {
    const float* psi_re = (const float*)d_in[0];
    const float* psi_im = (const float*)d_in[1];
    const float* U_re   = (const float*)d_in[2];
    const float* U_im   = (const float*)d_in[3];
    // d_in[4..7]: projector matrices — fixed DeGrand-Rossi I -/+ gamma_mu,
    // rank-2 structure exploited analytically.
    float* out = (float*)d_out;

    dslash_kernel<<<VOL / NT, NT>>>(psi_re, psi_im, U_re, U_im, out);
}

// round 11
// speedup vs baseline: 1.0362x; 1.0362x over previous
#include <cuda_runtime.h>
#include <cuda_bf16.h>
#include <cstdint>

// Wilson Dslash, 32^4 lattice, half-spinor formulation.
// l1tex-bound -> psi t-lines (contiguous 1536B) move on the bulk-copy engine
// (cp.async.bulk, bypasses l1tex), now DOUBLE-BUFFERED one stage ahead so the
// mbarrier wait is always behind a full stage of U staging + compute.
// U (36B-strided rows) stays scalar coalesced LDG->STS, conflict-free stride-9
// readback. Output: scale -> conflict-free STS -> bulk store.
// 128-thread blocks (4 warps), fully warp-local, no block barriers.
// Stage order s=0..7: (mu=s>>1, hop=s&1); copies for stages 0..6
// (stage 6 = own mu=3 line, stage 7 reuses it). Buffer = stage parity.

#define LAT 32
#define VOL (LAT * LAT * LAT * LAT)
#define NT 128
#define NWARP (NT / 32)

__device__ __forceinline__ uint32_t smem_u32(const void* p) {
    uint32_t a;
    asm("{ .reg .u64 t; cvta.to.shared.u64 t, %1; cvt.u32.u64 %0, t; }"
        : "=r"(a) : "l"(p));
    return a;
}

__device__ __forceinline__ void mbar_wait(uint32_t mb, int phase) {
    uint32_t done;
    do {
        asm volatile(
            "{ .reg .pred p; "
            "mbarrier.try_wait.parity.acquire.cta.shared::cta.b64 p, [%1], %2; "
            "selp.b32 %0, 1, 0, p; }"
            : "=r"(done) : "r"(mb), "r"(phase) : "memory");
    } while (!done);
}

__global__ __launch_bounds__(NT, 4)
void dslash_kernel(const float* __restrict__ psi_re, const float* __restrict__ psi_im,
                   const float* __restrict__ U_re,   const float* __restrict__ U_im,
                   float* __restrict__ out)
{
    __shared__ float4 sP[NWARP][2][2][96];   // [warp][buf][re/im][32 sites x 3 float4]
    __shared__ float  sUr[NWARP][288];       // one t-line of U (32 sites x 9)
    __shared__ float  sUi[NWARP][288];
    __shared__ __align__(8) unsigned long long mbar[NWARP][2];

    const int lane   = threadIdx.x & 31;
    const int w      = threadIdx.x >> 5;
    const int base_w = blockIdx.x * NT + w * 32;   // 32-aligned t-line base

    // line offsets per axis (warp-uniform)
    int fd[4], bd[4];
#pragma unroll
    for (int mu = 0; mu < 4; mu++) {
        const int shift = (mu == 0) ? 15 : (mu == 1) ? 10 : (mu == 2) ? 5 : 0;
        const int sm = 1 << shift;
        const int cmw = (base_w >> shift) & 31;
        fd[mu] = (cmw == 31) ? -31 * sm : sm;
        bd[mu] = (cmw == 0)  ?  31 * sm : -sm;
    }

    const uint32_t mb0 = smem_u32(&mbar[w][0]);
    const uint32_t mb1 = smem_u32(&mbar[w][1]);
    const uint32_t pR0 = smem_u32(&sP[w][0][0][0]);
    const uint32_t pI0 = smem_u32(&sP[w][0][1][0]);
    const uint32_t pR1 = smem_u32(&sP[w][1][0][0]);
    const uint32_t pI1 = smem_u32(&sP[w][1][1][0]);

    if (lane == 0) {
        asm volatile("mbarrier.init.shared.b64 [%0], 1;" :: "r"(mb0) : "memory");
        asm volatile("mbarrier.init.shared.b64 [%0], 1;" :: "r"(mb1) : "memory");
    }
    __syncwarp();

    // issue a psi-line bulk copy (lane 0; warp-uniform args)
    auto issue = [&](int line, uint32_t mb, uint32_t dr, uint32_t di) {
        if (lane == 0) {
            asm volatile("fence.proxy.async.shared::cta;" ::: "memory");
            asm volatile("mbarrier.arrive.expect_tx.shared.b64 _, [%0], %1;"
                         :: "r"(mb), "r"(3072) : "memory");
            const float* sr = psi_re + (size_t)line * 12;
            const float* si = psi_im + (size_t)line * 12;
            asm volatile(
                "cp.async.bulk.shared::cluster.global.mbarrier::complete_tx::bytes "
                "[%0], [%1], %2, [%3];" :: "r"(dr), "l"(sr), "r"(1536), "r"(mb) : "memory");
            asm volatile(
                "cp.async.bulk.shared::cluster.global.mbarrier::complete_tx::bytes "
                "[%0], [%1], %2, [%3];" :: "r"(di), "l"(si), "r"(1536), "r"(mb) : "memory");
        }
    };

    int ph0 = 0, ph1 = 0;

    // prologue: copy for stage 0 (fwd, mu=0) into buf0
    issue(base_w + fd[0], mb0, pR0, pI0);

    float accr[12], acci[12];
#pragma unroll
    for (int k = 0; k < 12; k++) { accr[k] = 0.f; acci[k] = 0.f; }

#pragma unroll
    for (int mu = 0; mu < 4; mu++) {
#pragma unroll 1
        for (int hop = 0; hop < 2; hop++) {   // 0 = fwd (P-, U), 1 = bwd (P+, U^dag)
            const float s = hop ? 1.f : -1.f;
            const int bufc = (mu == 3) ? 0 : hop;   // buffer holding this stage's psi

            // ---- issue NEXT stage's psi copy into the other buffer ----
            if (mu < 3) {
                if (hop == 0) {
                    issue(base_w + bd[mu], mb1, pR1, pI1);            // next: (mu, bwd)
                } else {
                    const int nline = (mu < 2) ? base_w + fd[mu + 1]  // next: (mu+1, fwd)
                                               : base_w;              // next: own mu=3 line
                    issue(nline, mb0, pR0, pI0);
                }
            }

            // ---- stage U t-line (coalesced scalar; TMA latency hides here) ----
            const bool load_u = (mu < 3) || (hop == 0);
            if (load_u) {
                const int ubase = (mu < 3 && hop) ? (base_w + bd[mu]) : base_w;
#pragma unroll
                for (int it = 0; it < 9; it++) {
                    const int idx = it * 32 + lane;
                    const int l = idx / 9;
                    const int k = idx - l * 9;
                    const size_t g = ((size_t)(ubase + l) * 4 + mu) * 9 + k;
                    sUr[w][idx] = U_re[g];
                    sUi[w][idx] = U_im[g];
                }
            }
            __syncwarp();   // U visible; also orders prior-stage reads before reuse

            // ---- wait for this stage's psi copy (stages 0..6) ----
            if ((mu < 3) || (hop == 0)) {
                if (bufc == 0) { mbar_wait(mb0, ph0); ph0 ^= 1; }
                else           { mbar_wait(mb1, ph1); ph1 ^= 1; }
            }

            // ---- read neighbor spinor from smem (conflict-free LDS.128) ----
            const float4* PR = (bufc == 0) ? &sP[w][0][0][0] : &sP[w][1][0][0];
            const float4* PI = (bufc == 0) ? &sP[w][0][1][0] : &sP[w][1][1][0];
            const int psl = (mu == 3) ? ((lane + (hop ? 31 : 1)) & 31) : lane;
            float pr[12], pi[12];
#pragma unroll
            for (int r = 0; r < 3; r++) {
                float4 a = PR[psl * 3 + r];
                pr[4*r+0] = a.x; pr[4*r+1] = a.y; pr[4*r+2] = a.z; pr[4*r+3] = a.w;
                float4 b = PI[psl * 3 + r];
                pi[4*r+0] = b.x; pi[4*r+1] = b.y; pi[4*r+2] = b.z; pi[4*r+3] = b.w;
            }

            // ---- project to half-spinor (mu static, s runtime) ----
            float hr0[3], hi0[3], hr1[3], hi1[3];
#pragma unroll
            for (int c = 0; c < 3; c++) {
                if (mu == 0) {          // h0 = p0 + s*i*p3 ; h1 = p1 + s*i*p2
                    hr0[c] = pr[c]   - s * pi[9+c];  hi0[c] = pi[c]   + s * pr[9+c];
                    hr1[c] = pr[3+c] - s * pi[6+c];  hi1[c] = pi[3+c] + s * pr[6+c];
                } else if (mu == 1) {   // h0 = p0 - s*p3 ; h1 = p1 + s*p2
                    hr0[c] = pr[c]   - s * pr[9+c];  hi0[c] = pi[c]   - s * pi[9+c];
                    hr1[c] = pr[3+c] + s * pr[6+c];  hi1[c] = pi[3+c] + s * pi[6+c];
                } else if (mu == 2) {   // h0 = p0 + s*i*p2 ; h1 = p1 - s*i*p3
                    hr0[c] = pr[c]   - s * pi[6+c];  hi0[c] = pi[c]   + s * pr[6+c];
                    hr1[c] = pr[3+c] + s * pi[9+c];  hi1[c] = pi[3+c] - s * pr[9+c];
                } else {                // h0 = p0 + s*p2 ; h1 = p1 + s*p3
                    hr0[c] = pr[c]   + s * pr[6+c];  hi0[c] = pi[c]   + s * pi[6+c];
                    hr1[c] = pr[3+c] + s * pr[9+c];  hi1[c] = pi[3+c] + s * pi[9+c];
                }
            }

            // ---- U read + color matvec: static per-hop branch ----
            const int usl = (mu == 3 && hop) ? ((lane + 31) & 31) : lane;
            const float* br = &sUr[w][usl * 9];
            const float* bi = &sUi[w][usl * 9];

            float xr0[3], xi0[3], xr1[3], xi1[3];
            if (hop == 0) {
#pragma unroll
                for (int i = 0; i < 3; i++) {
                    float r0 = 0.f, m0 = 0.f, r1 = 0.f, m1 = 0.f;
#pragma unroll
                    for (int j = 0; j < 3; j++) {
                        const float a = br[3*i+j], b = bi[3*i+j];
                        r0 += a * hr0[j] - b * hi0[j];
                        m0 += a * hi0[j] + b * hr0[j];
                        r1 += a * hr1[j] - b * hi1[j];
                        m1 += a * hi1[j] + b * hr1[j];
                    }
                    xr0[i] = r0; xi0[i] = m0; xr1[i] = r1; xi1[i] = m1;
                }
            } else {
#pragma unroll
                for (int i = 0; i < 3; i++) {
                    float r0 = 0.f, m0 = 0.f, r1 = 0.f, m1 = 0.f;
#pragma unroll
                    for (int j = 0; j < 3; j++) {
                        const float a = br[3*j+i], b = bi[3*j+i];   // U^dag
                        r0 += a * hr0[j] + b * hi0[j];
                        m0 += a * hi0[j] - b * hr0[j];
                        r1 += a * hr1[j] + b * hi1[j];
                        m1 += a * hi1[j] - b * hr1[j];
                    }
                    xr0[i] = r0; xi0[i] = m0; xr1[i] = r1; xi1[i] = m1;
                }
            }

            // ---- accumulate with spin reconstruction ----
#pragma unroll
            for (int i = 0; i < 3; i++) {
                accr[i]   += xr0[i];  acci[i]   += xi0[i];
                accr[3+i] += xr1[i];  acci[3+i] += xi1[i];
                if (mu == 0) {          // acc2 += -s*i*x1 ; acc3 += -s*i*x0
                    accr[6+i] += s * xi1[i];  acci[6+i] -= s * xr1[i];
                    accr[9+i] += s * xi0[i];  acci[9+i] -= s * xr0[i];
                } else if (mu == 1) {   // acc2 += s*x1 ; acc3 += -s*x0
                    accr[6+i] += s * xr1[i];  acci[6+i] += s * xi1[i];
                    accr[9+i] -= s * xr0[i];  acci[9+i] -= s * xi0[i];
                } else if (mu == 2) {   // acc2 += -s*i*x0 ; acc3 += s*i*x1
                    accr[6+i] += s * xi0[i];  acci[6+i] -= s * xr0[i];
                    accr[9+i] -= s * xi1[i];  acci[9+i] += s * xr1[i];
                } else {                // acc2 += s*x0 ; acc3 += s*x1
                    accr[6+i] += s * xr0[i];  acci[6+i] += s * xi0[i];
                    accr[9+i] += s * xr1[i];  acci[9+i] += s * xi1[i];
                }
            }
            __syncwarp();   // all lanes done reading before buffer reuse next stage
        }
    }

    // ---- scale by -0.5, transpose into buf1 (free after stage 5), bulk-store ----
#pragma unroll
    for (int r = 0; r < 3; r++) {
        float4 a, b;
        a.x = -0.5f * accr[4*r+0]; a.y = -0.5f * accr[4*r+1];
        a.z = -0.5f * accr[4*r+2]; a.w = -0.5f * accr[4*r+3];
        b.x = -0.5f * acci[4*r+0]; b.y = -0.5f * acci[4*r+1];
        b.z = -0.5f * acci[4*r+2]; b.w = -0.5f * acci[4*r+3];
        sP[w][1][0][lane * 3 + r] = a;     // stride-3 float4: conflict-free
        sP[w][1][1][lane * 3 + r] = b;
    }
    __syncwarp();
    if (lane == 0) {
        asm volatile("fence.proxy.async.shared::cta;" ::: "memory");
        float* gr = out + (size_t)base_w * 12;
        float* gi = out + (size_t)(VOL + base_w) * 12;
        asm volatile("cp.async.bulk.global.shared::cta.bulk_group [%0], [%1], %2;"
                     :: "l"(gr), "r"(pR1), "r"(1536) : "memory");
        asm volatile("cp.async.bulk.global.shared::cta.bulk_group [%0], [%1], %2;"
                     :: "l"(gi), "r"(pI1), "r"(1536) : "memory");
        asm volatile("cp.async.bulk.commit_group;" ::: "memory");
        asm volatile("cp.async.bulk.wait_group 0;" ::: "memory");
    }
}

extern "C" void kernel_launch(void* const* d_in, const int* in_sizes, int n_in,
                              void* d_out, int out_size) {
    const float* psi_re = (const float*)d_in[0];
    const float* psi_im = (const float*)d_in[1];
    const float* U_re   = (const float*)d_in[2];
    const float* U_im   = (const float*)d_in[3];
    // d_in[4..7]: projector matrices — fixed DeGrand-Rossi I -/+ gamma_mu,
    // rank-2 structure exploited analytically.
    float* out = (float*)d_out;

    dslash_kernel<<<VOL / NT, NT>>>(psi_re, psi_im, U_re, U_im, out);
}